// round 11
// baseline (speedup 1.0000x reference)
#include <cuda_runtime.h>
#include <cuda_bf16.h>
#include <cuda_fp16.h>
#include <cstdint>

#define NN 50000
#define NE 800000
#define ALPHA 0.5f
#define CAP 128           // adjacency slots per node (Poisson(16): P(deg>128) ~ 0)

// ---------------- scratch (device globals) -----------------------------------
__device__ int    g_deg[2 * NN];                 // cursor+degree; reset by k_gather
__device__ int    g_adj[(size_t)2 * NN * CAP];   // [0,NN): fwd lists, [NN,2NN): bwd
__device__ __half g_yh[(size_t)NN * 256];        // fp16 y, deg-scaled

__device__ __forceinline__ uint32_t smem_u32(const void* p) {
    uint32_t a;
    asm("{ .reg .u64 t; cvta.to.shared.u64 t, %1; cvt.u32.u64 %0, t; }" : "=r"(a) : "l"(p));
    return a;
}
__device__ __forceinline__ void ldsm_x4(uint32_t* r, uint32_t addr) {
    asm volatile("ldmatrix.sync.aligned.m8n8.x4.shared.b16 {%0,%1,%2,%3}, [%4];"
        : "=r"(r[0]), "=r"(r[1]), "=r"(r[2]), "=r"(r[3]) : "r"(addr));
}
__device__ __forceinline__ void ldsm_x4_t(uint32_t* r, uint32_t addr) {
    asm volatile("ldmatrix.sync.aligned.m8n8.x4.trans.shared.b16 {%0,%1,%2,%3}, [%4];"
        : "=r"(r[0]), "=r"(r[1]), "=r"(r[2]), "=r"(r[3]) : "r"(addr));
}
__device__ __forceinline__ void mma_bf16(float* c, const uint32_t* a, const uint32_t* b) {
    asm volatile(
        "mma.sync.aligned.m16n8k16.row.col.f32.bf16.bf16.f32 "
        "{%0,%1,%2,%3}, {%4,%5,%6,%7}, {%8,%9}, {%0,%1,%2,%3};"
        : "+f"(c[0]), "+f"(c[1]), "+f"(c[2]), "+f"(c[3])
        : "r"(a[0]), "r"(a[1]), "r"(a[2]), "r"(a[3]), "r"(b[0]), "r"(b[1]));
}
__device__ __forceinline__ float dinv_of(int idx) {
    int d = g_deg[idx];
    return (d > 0) ? rsqrtf((float)d) : 0.0f;
}

// ---------------- fill: direct-indexed adjacency, 4 edges/thread -------------
__global__ void k_fill(const int* __restrict__ row, const int* __restrict__ col,
                       int E, int N) {
    int t = blockIdx.x * blockDim.x + threadIdx.x;
    int e = t * 4;
    if (e + 3 < E) {
        int4 r = *(const int4*)(row + e);
        int4 c = *(const int4*)(col + e);
        int p0 = atomicAdd(&g_deg[r.x], 1);
        int p1 = atomicAdd(&g_deg[r.y], 1);
        int p2 = atomicAdd(&g_deg[r.z], 1);
        int p3 = atomicAdd(&g_deg[r.w], 1);
        int q0 = atomicAdd(&g_deg[N + c.x], 1);
        int q1 = atomicAdd(&g_deg[N + c.y], 1);
        int q2 = atomicAdd(&g_deg[N + c.z], 1);
        int q3 = atomicAdd(&g_deg[N + c.w], 1);
        if (p0 < CAP) g_adj[(size_t)r.x * CAP + p0] = c.x;
        if (p1 < CAP) g_adj[(size_t)r.y * CAP + p1] = c.y;
        if (p2 < CAP) g_adj[(size_t)r.z * CAP + p2] = c.z;
        if (p3 < CAP) g_adj[(size_t)r.w * CAP + p3] = c.w;
        if (q0 < CAP) g_adj[(size_t)(N + c.x) * CAP + q0] = r.x;
        if (q1 < CAP) g_adj[(size_t)(N + c.y) * CAP + q1] = r.y;
        if (q2 < CAP) g_adj[(size_t)(N + c.z) * CAP + q2] = r.z;
        if (q3 < CAP) g_adj[(size_t)(N + c.w) * CAP + q3] = r.w;
    } else {
        for (; e < E; e++) {
            int r = row[e], c = col[e];
            int p = atomicAdd(&g_deg[r], 1);
            if (p < CAP) g_adj[(size_t)r * CAP + p] = c;
            int q = atomicAdd(&g_deg[N + c], 1);
            if (q < CAP) g_adj[(size_t)(N + c) * CAP + q] = r;
        }
    }
}

// ---------------- HMMA bf16-split GEMM ---------------------------------------
#define SA_HI 0
#define SA_LO 32768
#define SB_HI 65536
#define SB_LO 131072
#define SM_TOT 196608

__global__ __launch_bounds__(256, 1) void k_gemm_mma(const float* __restrict__ X,
                                                     const float* __restrict__ Ws,
                                                     const float* __restrict__ Wd,
                                                     int M, int N) {
    extern __shared__ char sm[];
    uint32_t sb = smem_u32(sm);
    int tid = threadIdx.x, lane = tid & 31, wid = tid >> 5;
    int m0 = blockIdx.x * 128;

#pragma unroll
    for (int it = 0; it < 16; it++) {
        int i = it * 256 + tid;
        int row = i >> 5, c4 = (i & 31) << 2;
        int m = m0 + row;
        float4 v = make_float4(0.f, 0.f, 0.f, 0.f);
        if (m < M) v = *(const float4*)(X + (size_t)m * 128 + c4);
        uint32_t off = (uint32_t)row * 256u + (((uint32_t)c4 * 2u) ^ (((uint32_t)row & 7u) << 4));
        __nv_bfloat16 h[4], l2[4];
        float vv[4] = {v.x, v.y, v.z, v.w};
#pragma unroll
        for (int jj = 0; jj < 4; jj++) {
            h[jj]  = __float2bfloat16(vv[jj]);
            l2[jj] = __float2bfloat16(vv[jj] - __bfloat162float(h[jj]));
        }
        *(uint2*)(sm + SA_HI + off) = *(uint2*)h;
        *(uint2*)(sm + SA_LO + off) = *(uint2*)l2;
    }

#pragma unroll
    for (int it = 0; it < 32; it++) {
        int i = it * 256 + tid;
        int k = i >> 6, n4 = (i & 63) << 2;
        float4 v; float sc;
        if (n4 < 128) { v = *(const float4*)(Ws + (size_t)k * 128 + n4); sc = ALPHA; }
        else          { v = *(const float4*)(Wd + (size_t)k * 128 + (n4 - 128)); sc = 1.0f - ALPHA; }
        float vv[4] = {v.x * sc, v.y * sc, v.z * sc, v.w * sc};
        uint32_t off = (uint32_t)k * 512u + (((uint32_t)n4 * 2u) ^ (((uint32_t)k & 7u) << 4));
        __nv_bfloat16 h[4], l2[4];
#pragma unroll
        for (int jj = 0; jj < 4; jj++) {
            h[jj]  = __float2bfloat16(vv[jj]);
            l2[jj] = __float2bfloat16(vv[jj] - __bfloat162float(h[jj]));
        }
        *(uint2*)(sm + SB_HI + off) = *(uint2*)h;
        *(uint2*)(sm + SB_LO + off) = *(uint2*)l2;
    }
    __syncthreads();

    int wm = wid >> 2, wn = wid & 3;
    int g = lane >> 3, j = lane & 7;
    int arow_l = ((g & 1) << 3) + j;
    int akc16  = (g >> 1) << 4;
    int bkrow_l = ((g & 1) << 3) + j;
    int bnc8   = (g >> 1) << 3;

#pragma unroll
    for (int np = 0; np < 2; np++) {
        int n0w = np * 128 + wn * 32;
        float acc[4][4][4];
#pragma unroll
        for (int a = 0; a < 4; a++)
#pragma unroll
            for (int b = 0; b < 4; b++)
#pragma unroll
                for (int c = 0; c < 4; c++) acc[a][b][c] = 0.f;

#pragma unroll
        for (int ks = 0; ks < 8; ks++) {
            uint32_t ah[4][4], al[4][4];
#pragma unroll
            for (int fm = 0; fm < 4; fm++) {
                int row = wm * 64 + fm * 16 + arow_l;
                uint32_t ao = (uint32_t)row * 256u
                            + (((uint32_t)(ks * 32 + akc16)) ^ ((uint32_t)j << 4));
                ldsm_x4(ah[fm], sb + SA_HI + ao);
                ldsm_x4(al[fm], sb + SA_LO + ao);
            }
            uint32_t bh[4][2], bl[4][2];
#pragma unroll
            for (int fn2 = 0; fn2 < 2; fn2++) {
                int krow = ks * 16 + bkrow_l;
                uint32_t bo = (uint32_t)krow * 512u
                            + (((uint32_t)((n0w + fn2 * 16 + bnc8) * 2)) ^ ((uint32_t)j << 4));
                uint32_t r[4];
                ldsm_x4_t(r, sb + SB_HI + bo);
                bh[fn2 * 2][0] = r[0]; bh[fn2 * 2][1] = r[1];
                bh[fn2 * 2 + 1][0] = r[2]; bh[fn2 * 2 + 1][1] = r[3];
                ldsm_x4_t(r, sb + SB_LO + bo);
                bl[fn2 * 2][0] = r[0]; bl[fn2 * 2][1] = r[1];
                bl[fn2 * 2 + 1][0] = r[2]; bl[fn2 * 2 + 1][1] = r[3];
            }
#pragma unroll
            for (int fm = 0; fm < 4; fm++)
#pragma unroll
                for (int fn = 0; fn < 4; fn++) {
                    mma_bf16(acc[fm][fn], ah[fm], bh[fn]);
                    mma_bf16(acc[fm][fn], ah[fm], bl[fn]);
                    mma_bf16(acc[fm][fn], al[fm], bh[fn]);
                }
        }

#pragma unroll
        for (int fm = 0; fm < 4; fm++) {
            int r0 = m0 + wm * 64 + fm * 16 + (lane >> 2);
            int r1 = r0 + 8;
            float s0 = 0.f, s1 = 0.f;
            if (r0 < M) s0 = (np == 0) ? dinv_of(N + r0) : dinv_of(r0);
            if (r1 < M) s1 = (np == 0) ? dinv_of(N + r1) : dinv_of(r1);
#pragma unroll
            for (int fn = 0; fn < 4; fn++) {
                int col = n0w + fn * 8 + (lane & 3) * 2;
                if (r0 < M) {
                    *(__half2*)(g_yh + (size_t)r0 * 256 + col) =
                        __floats2half2_rn(acc[fm][fn][0] * s0, acc[fm][fn][1] * s0);
                }
                if (r1 < M) {
                    *(__half2*)(g_yh + (size_t)r1 * 256 + col) =
                        __floats2half2_rn(acc[fm][fn][2] * s1, acc[fm][fn][3] * s1);
                }
            }
        }
    }
}

// ---------------- gather (fp16 y, fp32 accumulate) ----------------------------
__device__ __forceinline__ void acc_h4(float4& a, uint2 v) {
    float2 f0 = __half22float2(*(__half2*)&v.x);
    float2 f1 = __half22float2(*(__half2*)&v.y);
    a.x += f0.x; a.y += f0.y; a.z += f1.x; a.w += f1.y;
}

__global__ __launch_bounds__(256) void k_gather(const float* __restrict__ bsrc,
                                                const float* __restrict__ bdst,
                                                float* __restrict__ out, int N) {
    int wid  = (blockIdx.x * blockDim.x + threadIdx.x) >> 5;
    int lane = threadIdx.x & 31;
    if (wid >= N) return;
    int n = wid;
    const uint2* __restrict__ Y = (const uint2*)g_yh;

    float4 accf = make_float4(0.f, 0.f, 0.f, 0.f);
    float4 accb = make_float4(0.f, 0.f, 0.f, 0.f);

    int degf = g_deg[n];
    int degb = g_deg[N + n];
    int ef = (degf < CAP) ? degf : CAP;
    int eb = (degb < CAP) ? degb : CAP;
    const int* __restrict__ lf = g_adj + (size_t)n * CAP;
    const int* __restrict__ lb = g_adj + (size_t)(N + n) * CAP;

    int j = 0;
    for (; j + 4 <= ef; j += 4) {
        int c0 = lf[j], c1 = lf[j + 1], c2 = lf[j + 2], c3 = lf[j + 3];
        uint2 v0 = Y[(size_t)c0 * 64 + lane];
        uint2 v1 = Y[(size_t)c1 * 64 + lane];
        uint2 v2 = Y[(size_t)c2 * 64 + lane];
        uint2 v3 = Y[(size_t)c3 * 64 + lane];
        acc_h4(accf, v0); acc_h4(accf, v1); acc_h4(accf, v2); acc_h4(accf, v3);
    }
    for (; j < ef; j++) acc_h4(accf, Y[(size_t)lf[j] * 64 + lane]);

    j = 0;
    for (; j + 4 <= eb; j += 4) {
        int r0 = lb[j], r1 = lb[j + 1], r2 = lb[j + 2], r3 = lb[j + 3];
        uint2 v0 = Y[(size_t)r0 * 64 + 32 + lane];
        uint2 v1 = Y[(size_t)r1 * 64 + 32 + lane];
        uint2 v2 = Y[(size_t)r2 * 64 + 32 + lane];
        uint2 v3 = Y[(size_t)r3 * 64 + 32 + lane];
        acc_h4(accb, v0); acc_h4(accb, v1); acc_h4(accb, v2); acc_h4(accb, v3);
    }
    for (; j < eb; j++) acc_h4(accb, Y[(size_t)lb[j] * 64 + 32 + lane]);

    float df = (degf > 0) ? rsqrtf((float)degf) : 0.0f;
    float db = (degb > 0) ? rsqrtf((float)degb) : 0.0f;
    float4 bs = ((const float4*)bsrc)[lane];
    float4 bd = ((const float4*)bdst)[lane];
    float4 o;
    o.x = ALPHA * bs.x + (1.0f - ALPHA) * bd.x + df * accf.x + db * accb.x;
    o.y = ALPHA * bs.y + (1.0f - ALPHA) * bd.y + df * accf.y + db * accb.y;
    o.z = ALPHA * bs.z + (1.0f - ALPHA) * bd.z + df * accf.z + db * accb.z;
    o.w = ALPHA * bs.w + (1.0f - ALPHA) * bd.w + df * accf.w + db * accb.w;
    ((float4*)out)[(size_t)n * 32 + lane] = o;

    // Reset degree state for the next run (warp owns node n exclusively).
    if (lane == 0) { g_deg[n] = 0; g_deg[N + n] = 0; }
}

// ---------------- launch ------------------------------------------------------
extern "C" void kernel_launch(void* const* d_in, const int* in_sizes, int n_in,
                              void* d_out, int out_size) {
    const float* x    = (const float*)d_in[0];
    const int*   ei   = (const int*)d_in[1];
    const float* Wsrc = (const float*)d_in[2];
    const float* bsrc = (const float*)d_in[3];
    const float* Wdst = (const float*)d_in[4];
    const float* bdst = (const float*)d_in[5];
    float*       out  = (float*)d_out;

    int N = in_sizes[0] / 128;
    int E = in_sizes[1] / 2;
    if (N > NN || E > NE) return;

    int equads = (E + 3) / 4;

    const int* row = ei;
    const int* col = ei + E;

    cudaFuncSetAttribute(k_gemm_mma, cudaFuncAttributeMaxDynamicSharedMemorySize, SM_TOT);

    k_fill<<<(equads + 255) / 256, 256>>>(row, col, E, N);
    k_gemm_mma<<<(N + 127) / 128, 256, SM_TOT>>>(x, Wsrc, Wdst, N, N);
    k_gather<<<(N * 32 + 255) / 256, 256>>>(bsrc, bdst, out, N);
}